// round 5
// baseline (speedup 1.0000x reference)
#include <cuda_runtime.h>
#include <math.h>

#define NB 16
#define NT 2048
#define ND 512
#define NH 512
#define SIXH 3072
#define MROWS (NB * NT)   // 32768

#define GRID2 128
#define THR2 256
// smem: sh_h 512*16 | sh_wt 512*48 (dup-pair) | red 2 banks x 1440 u64
#define SMEM2_FLOATS (8192 + 24576 + 2 * 2880)
#define SMEM2_BYTES (SMEM2_FLOATS * 4)

typedef unsigned long long u64;

// ---------------- device scratch (static: no runtime allocation) ----------------
__device__ float g_pi[(size_t)MROWS * SIXH];   // 402 MB: PI = X @ W^T + b
__device__ float g_ht[2][NH * NB];             // h double buffer, layout [k][b]
__device__ unsigned int g_hflag[GRID2];        // per-CTA monotonic publish counters

// ---------------- packed f32x2 helpers (SASS FFMA2 — exact fp32 numerics) -------
__device__ __forceinline__ u64 pack2(float lo, float hi) {
    u64 r;
    asm("mov.b64 %0, {%1, %2};" : "=l"(r) : "f"(lo), "f"(hi));
    return r;
}
__device__ __forceinline__ void unpack2(u64 v, float& lo, float& hi) {
    asm("mov.b64 {%0, %1}, %2;" : "=f"(lo), "=f"(hi) : "l"(v));
}
__device__ __forceinline__ void fma2(u64& d, u64 a, u64 b) {
    asm("fma.rn.f32x2 %0, %1, %2, %0;" : "+l"(d) : "l"(a), "l"(b));
}

// ---------------- math helpers ----------------
__device__ __forceinline__ float sigf(float x) {
    return 1.0f / (1.0f + __expf(-x));
}
__device__ __forceinline__ float tanh_acc(float x) {
    float e = __expf(-2.0f * fabsf(x));
    float t = (1.0f - e) / (1.0f + e);
    return x >= 0.0f ? t : -t;
}

// =====================================================================
// Phase 1: PI = X @ W^T + b (FFMA2 SGEMM, near fp32 roofline) — unchanged
// =====================================================================
#define BK1 16
#define LDA1 132

__global__ void __launch_bounds__(256) gemm_pi_kernel(
    const float* __restrict__ X, const float* __restrict__ W,
    const float* __restrict__ bias)
{
    __shared__ float As[BK1 * LDA1];
    __shared__ float Bs[BK1 * LDA1];

    const int tid = threadIdx.x;
    const int tx = tid & 15, ty = tid >> 4;
    const int n0 = blockIdx.x * 128;
    const int m0 = blockIdx.y * 128;

    const float* Xp = X + (size_t)m0 * ND;
    const float* Wp = W + (size_t)n0 * ND;

    u64 accP[8][4];
#pragma unroll
    for (int i = 0; i < 8; i++)
#pragma unroll
        for (int j = 0; j < 4; j++) accP[i][j] = 0ULL;

    for (int kc = 0; kc < ND; kc += BK1) {
#pragma unroll
        for (int i = 0; i < 2; i++) {
            int idx4 = tid + 256 * i;
            int row = idx4 >> 2;
            int kq = idx4 & 3;
            float4 va = *(const float4*)(Xp + (size_t)row * ND + kc + kq * 4);
            float4 vb = *(const float4*)(Wp + (size_t)row * ND + kc + kq * 4);
            As[(kq * 4 + 0) * LDA1 + row] = va.x;
            As[(kq * 4 + 1) * LDA1 + row] = va.y;
            As[(kq * 4 + 2) * LDA1 + row] = va.z;
            As[(kq * 4 + 3) * LDA1 + row] = va.w;
            Bs[(kq * 4 + 0) * LDA1 + row] = vb.x;
            Bs[(kq * 4 + 1) * LDA1 + row] = vb.y;
            Bs[(kq * 4 + 2) * LDA1 + row] = vb.z;
            Bs[(kq * 4 + 3) * LDA1 + row] = vb.w;
        }
        __syncthreads();

#pragma unroll
        for (int k = 0; k < BK1; k++) {
            float a[8];
            *(float4*)&a[0] = *(const float4*)&As[k * LDA1 + ty * 8];
            *(float4*)&a[4] = *(const float4*)&As[k * LDA1 + ty * 8 + 4];
            ulonglong2 b01 = *(const ulonglong2*)&Bs[k * LDA1 + tx * 8];
            ulonglong2 b23 = *(const ulonglong2*)&Bs[k * LDA1 + tx * 8 + 4];
#pragma unroll
            for (int i = 0; i < 8; i++) {
                u64 ad = pack2(a[i], a[i]);
                fma2(accP[i][0], b01.x, ad);
                fma2(accP[i][1], b01.y, ad);
                fma2(accP[i][2], b23.x, ad);
                fma2(accP[i][3], b23.y, ad);
            }
        }
        __syncthreads();
    }

    float bv[8];
#pragma unroll
    for (int j = 0; j < 8; j++) bv[j] = bias[n0 + tx * 8 + j];

#pragma unroll
    for (int i = 0; i < 8; i++) {
        float c[8];
#pragma unroll
        for (int jp = 0; jp < 4; jp++)
            unpack2(accP[i][jp], c[2 * jp], c[2 * jp + 1]);
        size_t m = (size_t)m0 + ty * 8 + i;
        float* op = g_pi + m * SIXH + n0 + tx * 8;
        float4 r0 = make_float4(c[0] + bv[0], c[1] + bv[1],
                                c[2] + bv[2], c[3] + bv[3]);
        float4 r1 = make_float4(c[4] + bv[4], c[5] + bv[5],
                                c[6] + bv[6], c[7] + bv[7]);
        *(float4*)op = r0;
        *(float4*)(op + 4) = r1;
    }
}

// =====================================================================
// Phase 2: persistent recurrence, NO grid barrier.
// Producer/consumer protocol:
//   - g_hflag[p] is a monotonic counter. base = own flag at launch
//     (all equal: every launch advances every flag by exactly NT).
//   - publish h_s  =>  flag[p] = base + s + 1   (s = 0 .. NT-1)
//   - warp w consumes only producers 16w..16w+15 (its k-range):
//     lanes 0..15 poll with ld.acquire.gpu, then the warp copies its
//     4KB h region with __ldcg (L2-direct; no L1 staleness, no CCTL).
//   - red[] double-buffered by t&1 -> single __syncthreads per step.
// =====================================================================
__global__ void __launch_bounds__(THR2, 1) lstm_rec_kernel(
    const float* __restrict__ W, const float* __restrict__ bias,
    const int* __restrict__ lengths, float* __restrict__ out)
{
    extern __shared__ float smem[];
    float* sh_h  = smem;                   // [512][16]  k-major
    float* sh_wt = smem + 8192;            // [512][48]  dup-pair layout
    u64*   red   = (u64*)(smem + 8192 + 24576);  // 2 banks x [8bg][5g][4jg][9]

    const int tid = threadIdx.x;
    const int cta = blockIdx.x;
    const int jo_base = cta * 4;

    // --- build persistent duplicated W slice (once) ---
    for (int p = tid; p < 20 * 512; p += THR2) {
        int k = p & 511;
        int r = p >> 9;
        int g = r >> 2;
        int jg = r & 3;
        float v = W[(size_t)(g * NH + jo_base + jg) * ND + k];
        int base_i = k * 48 + jg * 12 + g * 2;
        sh_wt[base_i] = v;
        sh_wt[base_i + 1] = v;
    }

    // --- launch-local flag base (only this CTA ever writes flag[cta]) ---
    const unsigned fbase = *(volatile unsigned*)&g_hflag[cta];

    // --- combine-thread persistent state ---
    int b_c = 0, jo_c = 0, len_c = 0;
    float bias5[5] = {0, 0, 0, 0, 0};
    float c_reg = 0.0f;
    const float* pi_row = g_pi;
    if (tid < 64) {
        b_c = tid >> 2;
        jo_c = jo_base + (tid & 3);
#pragma unroll
        for (int g = 0; g < 5; g++) bias5[g] = bias[g * NH + jo_c];
        len_c = lengths[b_c];
        pi_row = g_pi + (size_t)b_c * NT * SIXH + jo_c;
    }

    // --- publish h_0 = zeros ---
    if (tid < 64) g_ht[0][cta * 64 + tid] = 0.0f;
    __threadfence();
    __syncthreads();
    if (tid == 0) {
        unsigned f0 = fbase + 1;
        asm volatile("st.global.relaxed.gpu.u32 [%0], %1;"
                     :: "l"(&g_hflag[cta]), "r"(f0) : "memory");
    }

    // prefetch PI(t=0)
    float pi5[5] = {0, 0, 0, 0, 0}, pi6 = 0.0f;
    if (tid < 64) {
#pragma unroll
        for (int g = 0; g < 5; g++) pi5[g] = pi_row[g * NH];
        pi6 = pi_row[5 * NH];
    }

    const int warp = tid >> 5, lane = tid & 31;
    const int bg = lane & 7;
    const int jg = lane >> 3;
    const u64*   hp0 = (const u64*)sh_h + (size_t)warp * 64 * 8 + bg;
    const float* wp0 = sh_wt + (size_t)warp * 64 * 48 + jg * 12;
    const unsigned* myflag = &g_hflag[warp * 16 + lane];  // lanes 0..15 use this

    for (int t = 0; t < NT; t++) {
        const float* hbuf = g_ht[t & 1];
        float* hnext = g_ht[(t & 1) ^ 1];

        // --- wait for the 16 producers this warp depends on ---
        if (lane < 16) {
            unsigned tgt = fbase + (unsigned)t + 1u;
            unsigned v;
            do {
                asm volatile("ld.global.acquire.gpu.u32 %0, [%1];"
                             : "=r"(v) : "l"(myflag) : "memory");
            } while ((int)(v - tgt) < 0);
        }
        __syncwarp();

        // --- stage this warp's 64x16 h region (L2-direct) ---
#pragma unroll
        for (int i = 0; i < 8; i++) {
            int off = warp * 1024 + i * 128 + lane * 4;
            float4 v = __ldcg((const float4*)(hbuf + off));
            *(float4*)&sh_h[off] = v;
        }
        __syncwarp();

        // --- K-split packed GEMM: {b0,b1} x 5 gates per lane, 64 k ---
        u64 acc0 = 0, acc1 = 0, acc2 = 0, acc3 = 0, acc4 = 0;
        {
            const u64* hp = hp0;
            const float* wp = wp0;
#pragma unroll 8
            for (int kk = 0; kk < 64; kk++) {
                u64 hd = *hp;
                ulonglong2 w01 = *(const ulonglong2*)wp;
                ulonglong2 w23 = *(const ulonglong2*)(wp + 4);
                u64 w44 = *(const u64*)(wp + 8);
                fma2(acc0, hd, w01.x);
                fma2(acc1, hd, w01.y);
                fma2(acc2, hd, w23.x);
                fma2(acc3, hd, w23.y);
                fma2(acc4, hd, w44);
                hp += 8;
                wp += 48;
            }
        }

        // write pair partials to this step's red bank
        {
            u64* redb = red + (t & 1) * 1440;
            int rb = (bg * 5) * 4 + jg;
            redb[(rb + 0) * 9 + warp] = acc0;
            redb[(rb + 4) * 9 + warp] = acc1;
            redb[(rb + 8) * 9 + warp] = acc2;
            redb[(rb + 12) * 9 + warp] = acc3;
            redb[(rb + 16) * 9 + warp] = acc4;
        }
        __syncthreads();   // the only CTA-wide sync per step

        // --- reduce + gate math + publish (warps 0,1) ---
        if (tid < 64) {
            const float* redf = (const float*)(red + (t & 1) * 1440);
            int bgc = b_c >> 1, e = b_c & 1, q = tid & 3;
            float gv[5];
#pragma unroll
            for (int g = 0; g < 5; g++) {
                const float* rp = redf + (((bgc * 5 + g) * 4 + q) * 9) * 2 + e;
                float s = ((rp[0] + rp[2]) + (rp[4] + rp[6])) +
                          ((rp[8] + rp[10]) + (rp[12] + rp[14]));
                gv[g] = s + bias5[g] + pi5[g];
            }
            float ig = sigf(gv[0]);
            float fg = sigf(gv[1]);
            float mi = tanh_acc(gv[2]);
            float og = sigf(gv[3]);
            float hwg = sigf(gv[4]);
            float mem = fmaf(ig, mi, fg * c_reg);
            float o_ = og * tanh_acc(mem);
            o_ = fmaf(hwg, o_ - pi6, pi6);
            if (t >= len_c) { o_ = 0.0f; mem = 0.0f; }
            c_reg = mem;

            hnext[jo_c * 16 + b_c] = o_;   // transposed h slice (256B/CTA)
            out[((size_t)b_c * NT + t) * NH + jo_c] = o_;

            __threadfence();                    // order h before flag
            asm volatile("bar.sync 1, 64;" ::: "memory");  // warps 0+1 only
            if (tid == 0 && t + 1 < NT) {
                unsigned fv = fbase + (unsigned)t + 2u;
                asm volatile("st.global.relaxed.gpu.u32 [%0], %1;"
                             :: "l"(&g_hflag[cta]), "r"(fv) : "memory");
            }

            // prefetch PI(t+1): off the inter-CTA critical path
            if (t + 1 < NT) {
                const float* pr = pi_row + (size_t)(t + 1) * SIXH;
#pragma unroll
                for (int g = 0; g < 5; g++) pi5[g] = pr[g * NH];
                pi6 = pr[5 * NH];
            }
        }
    }
}

// =====================================================================
// launch
// =====================================================================
extern "C" void kernel_launch(void* const* d_in, const int* in_sizes, int n_in,
                              void* d_out, int out_size) {
    const float* x = (const float*)d_in[0];
    const int* lengths = (const int*)d_in[1];
    const float* W = (const float*)d_in[2];
    const float* bias = (const float*)d_in[3];
    float* out = (float*)d_out;

    static bool attr_done = false;
    if (!attr_done) {
        cudaFuncSetAttribute(lstm_rec_kernel,
                             cudaFuncAttributeMaxDynamicSharedMemorySize,
                             SMEM2_BYTES);
        attr_done = true;
    }

    dim3 g1(SIXH / 128, MROWS / 128);  // (24, 256)
    gemm_pi_kernel<<<g1, 256>>>(x, W, bias);
    lstm_rec_kernel<<<GRID2, THR2, SMEM2_BYTES>>>(W, bias, lengths, out);
}

// round 6
// speedup vs baseline: 1.7557x; 1.7557x over previous
#include <cuda_runtime.h>
#include <math.h>

#define NB 16
#define NT 2048
#define ND 512
#define NH 512
#define SIXH 3072
#define MROWS (NB * NT)   // 32768

#define GRID2 128
#define THR2 288          // 8 compute warps + 1 combine warp

typedef unsigned long long u64;

// smem: sh_wt 512*48 | sh_h skewed 2176 f | red 4 banks x 360 u64
#define SH_WT_F (512 * 48)      // 24576 floats
#define SH_H_F  2176            // skewed h staging (1086 u64 used)
#define RED_U64 (4 * 360)       // 1440 u64
#define SMEM2_FLOATS (SH_WT_F + SH_H_F + 2 * RED_U64)
#define SMEM2_BYTES (SMEM2_FLOATS * 4)

// ---------------- device scratch ----------------
__device__ float g_pi[(size_t)MROWS * SIXH];   // PI = X @ W^T + b
__device__ float g_hg[4][2][ND * 4];           // per-chunk h, dbl-buffered, [k][4]
__device__ u64 g_cnt[4];                       // per-chunk monotonic counters
__device__ u64 g_bar_count;                    // init barrier counter

// ---------------- packed f32x2 helpers ----------------
__device__ __forceinline__ u64 pack2(float lo, float hi) {
    u64 r;
    asm("mov.b64 %0, {%1, %2};" : "=l"(r) : "f"(lo), "f"(hi));
    return r;
}
__device__ __forceinline__ void unpack2(u64 v, float& lo, float& hi) {
    asm("mov.b64 {%0, %1}, %2;" : "=f"(lo), "=f"(hi) : "l"(v));
}
__device__ __forceinline__ void fma2(u64& d, u64 a, u64 b) {
    asm("fma.rn.f32x2 %0, %1, %2, %0;" : "+l"(d) : "l"(a), "l"(b));
}
__device__ __forceinline__ u64 add2(u64 a, u64 b) {
    u64 r;
    asm("add.rn.f32x2 %0, %1, %2;" : "=l"(r) : "l"(a), "l"(b));
    return r;
}

__device__ __forceinline__ float sigf(float x) {
    return 1.0f / (1.0f + __expf(-x));
}
__device__ __forceinline__ float tanh_acc(float x) {
    float e = __expf(-2.0f * fabsf(x));
    float t = (1.0f - e) / (1.0f + e);
    return x >= 0.0f ? t : -t;
}

// =====================================================================
// Phase 1: PI = X @ W^T + b (FFMA2 SGEMM) — unchanged
// =====================================================================
#define BK1 16
#define LDA1 132

__global__ void __launch_bounds__(256) gemm_pi_kernel(
    const float* __restrict__ X, const float* __restrict__ W,
    const float* __restrict__ bias)
{
    __shared__ float As[BK1 * LDA1];
    __shared__ float Bs[BK1 * LDA1];

    const int tid = threadIdx.x;
    const int tx = tid & 15, ty = tid >> 4;
    const int n0 = blockIdx.x * 128;
    const int m0 = blockIdx.y * 128;

    const float* Xp = X + (size_t)m0 * ND;
    const float* Wp = W + (size_t)n0 * ND;

    u64 accP[8][4];
#pragma unroll
    for (int i = 0; i < 8; i++)
#pragma unroll
        for (int j = 0; j < 4; j++) accP[i][j] = 0ULL;

    for (int kc = 0; kc < ND; kc += BK1) {
#pragma unroll
        for (int i = 0; i < 2; i++) {
            int idx4 = tid + 256 * i;
            int row = idx4 >> 2;
            int kq = idx4 & 3;
            float4 va = *(const float4*)(Xp + (size_t)row * ND + kc + kq * 4);
            float4 vb = *(const float4*)(Wp + (size_t)row * ND + kc + kq * 4);
            As[(kq * 4 + 0) * LDA1 + row] = va.x;
            As[(kq * 4 + 1) * LDA1 + row] = va.y;
            As[(kq * 4 + 2) * LDA1 + row] = va.z;
            As[(kq * 4 + 3) * LDA1 + row] = va.w;
            Bs[(kq * 4 + 0) * LDA1 + row] = vb.x;
            Bs[(kq * 4 + 1) * LDA1 + row] = vb.y;
            Bs[(kq * 4 + 2) * LDA1 + row] = vb.z;
            Bs[(kq * 4 + 3) * LDA1 + row] = vb.w;
        }
        __syncthreads();

#pragma unroll
        for (int k = 0; k < BK1; k++) {
            float a[8];
            *(float4*)&a[0] = *(const float4*)&As[k * LDA1 + ty * 8];
            *(float4*)&a[4] = *(const float4*)&As[k * LDA1 + ty * 8 + 4];
            ulonglong2 b01 = *(const ulonglong2*)&Bs[k * LDA1 + tx * 8];
            ulonglong2 b23 = *(const ulonglong2*)&Bs[k * LDA1 + tx * 8 + 4];
#pragma unroll
            for (int i = 0; i < 8; i++) {
                u64 ad = pack2(a[i], a[i]);
                fma2(accP[i][0], b01.x, ad);
                fma2(accP[i][1], b01.y, ad);
                fma2(accP[i][2], b23.x, ad);
                fma2(accP[i][3], b23.y, ad);
            }
        }
        __syncthreads();
    }

    float bv[8];
#pragma unroll
    for (int j = 0; j < 8; j++) bv[j] = bias[n0 + tx * 8 + j];

#pragma unroll
    for (int i = 0; i < 8; i++) {
        float c[8];
#pragma unroll
        for (int jp = 0; jp < 4; jp++)
            unpack2(accP[i][jp], c[2 * jp], c[2 * jp + 1]);
        size_t m = (size_t)m0 + ty * 8 + i;
        float* op = g_pi + m * SIXH + n0 + tx * 8;
        float4 r0 = make_float4(c[0] + bv[0], c[1] + bv[1],
                                c[2] + bv[2], c[3] + bv[3]);
        float4 r1 = make_float4(c[4] + bv[4], c[5] + bv[5],
                                c[6] + bv[6], c[7] + bv[7]);
        *(float4*)op = r0;
        *(float4*)(op + 4) = r1;
    }
}

// one-shot init barrier (monotonic, replay-safe)
__device__ __forceinline__ void grid_barrier() {
    __syncthreads();
    if (threadIdx.x == 0) {
        __threadfence();
        u64 arrive = atomicAdd(&g_bar_count, 1ULL);
        u64 target = (arrive / GRID2 + 1ULL) * GRID2;
        if (arrive + 1ULL != target) {
            volatile u64* p = (volatile u64*)&g_bar_count;
            while (*p < target) { }
        }
        __threadfence();
    }
    __syncthreads();
}

// =====================================================================
// Phase 2: persistent recurrence with batch-chunk pipelining.
// 4 chunks of 4 batches per step; per-chunk aggregated counters; 8
// compute warps (K-split 16, shfl-reduce over ks) + 1 combine warp
// (reduce across warps, gate math, publish). Named barriers decouple
// compute from combine. Publish->consume latency hides behind the
// other 3 chunks' work.
// =====================================================================
__global__ void __launch_bounds__(THR2, 1) lstm_rec_kernel(
    const float* __restrict__ W, const float* __restrict__ bias,
    const int* __restrict__ lengths, float* __restrict__ out)
{
    extern __shared__ float smem[];
    float* sh_wt = smem;                        // [512][48] dup-pair
    float* sh_h  = smem + SH_WT_F;              // skewed staging
    u64*   red   = (u64*)(smem + SH_WT_F + SH_H_F);  // 4 banks x 360
    __shared__ float hpub[16];
    __shared__ u64 sbase[4];

    const int tid = threadIdx.x;
    const int cta = blockIdx.x;
    const int jo_base = cta * 4;

    // persistent duplicated W slice
    for (int p = tid; p < 20 * 512; p += THR2) {
        int k = p & 511, r = p >> 9;
        int u = r >> 2, jg = r & 3;
        float v = W[(size_t)(u * NH + jo_base + jg) * ND + k];
        int bi = k * 48 + jg * 12 + u * 2;
        sh_wt[bi] = v;
        sh_wt[bi + 1] = v;
    }
    // read counter bases BEFORE any CTA increments (barrier below)
    if (tid < 4) {
        u64 v;
        asm volatile("ld.global.cg.u64 %0, [%1];" : "=l"(v)
                     : "l"(&g_cnt[tid]) : "memory");
        sbase[tid] = v;
    }
    grid_barrier();

    if (tid >= 256) {
        // ================= combine warp =================
        const int t8 = tid - 256;
        const bool act = t8 < 16;
        const int bh = t8 >> 2, jg = t8 & 3;
        const int jo_c = jo_base + jg;
        float bias5[5] = {0, 0, 0, 0, 0};
        int len4[4] = {0, 0, 0, 0};
        float c4[4] = {0, 0, 0, 0};
        if (act) {
#pragma unroll
            for (int u = 0; u < 5; u++) bias5[u] = bias[u * NH + jo_c];
#pragma unroll
            for (int g = 0; g < 4; g++) len4[g] = lengths[g * 4 + bh];
        }
        // init-publish h_0 = 0 for all 4 chunks (own 4 rows each)
        if (t8 == 0) {
            float4 z = make_float4(0.f, 0.f, 0.f, 0.f);
#pragma unroll
            for (int g = 0; g < 4; g++) {
                float4* dst = (float4*)(&g_hg[g][0][jo_base * 4]);
                dst[0] = z; dst[1] = z; dst[2] = z; dst[3] = z;
                asm volatile("red.release.gpu.global.add.u64 [%0], %1;"
                             :: "l"(&g_cnt[g]), "l"(1ULL) : "memory");
            }
        }
        // prefetch PI(chunk 0, t=0)
        float pi5[5] = {0, 0, 0, 0, 0}, pi6 = 0.f;
        if (act) {
            const float* pr = g_pi + (size_t)bh * NT * SIXH + jo_c;
#pragma unroll
            for (int u = 0; u < 5; u++) pi5[u] = pr[u * NH];
            pi6 = pr[5 * NH];
        }

        for (int t = 0; t < NT; t++) {
#pragma unroll
            for (int gc = 0; gc < 4; gc++) {
                asm volatile("bar.sync %0, %1;" :: "r"(gc + 1), "n"(THR2)
                             : "memory");
                if (act) {
                    const int bgp = bh >> 1, e = bh & 1;
                    const float* redf = (const float*)(red + gc * 360);
                    float gv[5];
#pragma unroll
                    for (int u = 0; u < 5; u++) {
                        const float* rp =
                            redf + ((bgp * 5 + u) * 4 + jg) * 18 + e;
                        float s = ((rp[0] + rp[2]) + (rp[4] + rp[6])) +
                                  ((rp[8] + rp[10]) + (rp[12] + rp[14]));
                        gv[u] = s + bias5[u] + pi5[u];
                    }
                    float ig = sigf(gv[0]);
                    float fg = sigf(gv[1]);
                    float mi = tanh_acc(gv[2]);
                    float og = sigf(gv[3]);
                    float hw = sigf(gv[4]);
                    float mem = fmaf(ig, mi, fg * c4[gc]);
                    float o_ = og * tanh_acc(mem);
                    o_ = fmaf(hw, o_ - pi6, pi6);
                    if (t >= len4[gc]) { o_ = 0.f; mem = 0.f; }
                    c4[gc] = mem;
                    out[((size_t)(gc * 4 + bh) * NT + t) * NH + jo_c] = o_;
                    hpub[jg * 4 + bh] = o_;
                }
                __syncwarp();
                if (t8 == 0) {
                    const float4* hs = (const float4*)hpub;
                    float4 v0 = hs[0], v1 = hs[1], v2 = hs[2], v3 = hs[3];
                    float4* dst =
                        (float4*)(&g_hg[gc][(t + 1) & 1][jo_base * 4]);
                    dst[0] = v0; dst[1] = v1; dst[2] = v2; dst[3] = v3;
                    asm volatile("red.release.gpu.global.add.u64 [%0], %1;"
                                 :: "l"(&g_cnt[gc]), "l"(1ULL) : "memory");
                }
                __syncwarp();
                // prefetch next chunk's PI (hides under next bar.sync)
                int ng = (gc + 1) & 3;
                int nt = (gc == 3) ? t + 1 : t;
                if (act && nt < NT) {
                    const float* pr = g_pi +
                        ((size_t)(ng * 4 + bh) * NT + nt) * SIXH + jo_c;
#pragma unroll
                    for (int u = 0; u < 5; u++) pi5[u] = pr[u * NH];
                    pi6 = pr[5 * NH];
                }
            }
        }
    } else {
        // ================= compute warps =================
        const int warp = tid >> 5, lane = tid & 31;
        const int ks = lane >> 3;          // K sub-split (16 k each)
        const int bg = (lane >> 2) & 1;    // batch pair within chunk
        const int jg = lane & 3;           // channel offset
        u64* shh64 = (u64*)sh_h;
        // skewed staging layout: warp stride 136 u64, ks-group stride 34
        const u64*   hp0 = shh64 + warp * 136 + ks * 34 + bg;
        const float* wp0 = sh_wt + (size_t)(warp * 64 + ks * 16) * 48 + jg * 12;

        for (int t = 0; t < NT; t++) {
#pragma unroll
            for (int gc = 0; gc < 4; gc++) {
                if (lane == 0) {
                    u64 tgt = sbase[gc] + 128ULL * ((u64)t + 1ULL);
                    u64 v;
                    do {
                        asm volatile("ld.global.acquire.gpu.u64 %0, [%1];"
                                     : "=l"(v) : "l"(&g_cnt[gc]) : "memory");
                    } while (v < tgt);
                }
                __syncwarp();
                // stage this warp's 64 rows (skewed)
                {
                    const u64* src =
                        (const u64*)(&g_hg[gc][t & 1][0]) + warp * 128 + lane;
                    u64* dst = shh64 + warp * 136 + lane;
                    dst[0]          = __ldcg(src);
                    dst[34]         = __ldcg(src + 32);
                    dst[68]         = __ldcg(src + 64);
                    dst[102]        = __ldcg(src + 96);
                }
                __syncwarp();
                // 16-k packed microtile: {b0,b1} x 5 gates
                u64 a0 = 0, a1 = 0, a2 = 0, a3 = 0, a4 = 0;
                {
                    const u64* hp = hp0;
                    const float* wp = wp0;
#pragma unroll
                    for (int kk = 0; kk < 16; kk++) {
                        u64 hd = hp[kk * 2];
                        ulonglong2 w01 = *(const ulonglong2*)wp;
                        ulonglong2 w23 = *(const ulonglong2*)(wp + 4);
                        u64 w44 = *(const u64*)(wp + 8);
                        fma2(a0, hd, w01.x);
                        fma2(a1, hd, w01.y);
                        fma2(a2, hd, w23.x);
                        fma2(a3, hd, w23.y);
                        fma2(a4, hd, w44);
                        wp += 48;
                    }
                }
                // reduce over ks (lanes xor 8, xor 16)
                a0 = add2(a0, __shfl_xor_sync(0xffffffffu, a0, 8));
                a1 = add2(a1, __shfl_xor_sync(0xffffffffu, a1, 8));
                a2 = add2(a2, __shfl_xor_sync(0xffffffffu, a2, 8));
                a3 = add2(a3, __shfl_xor_sync(0xffffffffu, a3, 8));
                a4 = add2(a4, __shfl_xor_sync(0xffffffffu, a4, 8));
                a0 = add2(a0, __shfl_xor_sync(0xffffffffu, a0, 16));
                a1 = add2(a1, __shfl_xor_sync(0xffffffffu, a1, 16));
                a2 = add2(a2, __shfl_xor_sync(0xffffffffu, a2, 16));
                a3 = add2(a3, __shfl_xor_sync(0xffffffffu, a3, 16));
                a4 = add2(a4, __shfl_xor_sync(0xffffffffu, a4, 16));
                if (ks == 0) {
                    u64* redb = red + gc * 360;
                    int rb = (bg * 5) * 4 + jg;
                    redb[(rb +  0) * 9 + warp] = a0;
                    redb[(rb +  4) * 9 + warp] = a1;
                    redb[(rb +  8) * 9 + warp] = a2;
                    redb[(rb + 12) * 9 + warp] = a3;
                    redb[(rb + 16) * 9 + warp] = a4;
                }
                asm volatile("bar.arrive %0, %1;" :: "r"(gc + 1), "n"(THR2)
                             : "memory");
            }
        }
    }
}

// =====================================================================
// launch
// =====================================================================
extern "C" void kernel_launch(void* const* d_in, const int* in_sizes, int n_in,
                              void* d_out, int out_size) {
    const float* x = (const float*)d_in[0];
    const int* lengths = (const int*)d_in[1];
    const float* W = (const float*)d_in[2];
    const float* bias = (const float*)d_in[3];
    float* out = (float*)d_out;

    static bool attr_done = false;
    if (!attr_done) {
        cudaFuncSetAttribute(lstm_rec_kernel,
                             cudaFuncAttributeMaxDynamicSharedMemorySize,
                             SMEM2_BYTES);
        attr_done = true;
    }

    dim3 g1(SIXH / 128, MROWS / 128);  // (24, 256)
    gemm_pi_kernel<<<g1, 256>>>(x, W, bias);
    lstm_rec_kernel<<<GRID2, THR2, SMEM2_BYTES>>>(W, bias, lengths, out);
}

// round 7
// speedup vs baseline: 2.3560x; 1.3419x over previous
#include <cuda_runtime.h>
#include <math.h>

#define NB 16
#define NT 2048
#define ND 512
#define NH 512
#define SIXH 3072
#define MROWS (NB * NT)   // 32768

#define GRID2 128
#define THR2 256
#define NGRP 16
#define GRPSZ 8

// smem: sh_h 512*16 | sh_wt 512*48 (dup-pair) | red 1440 u64
#define SMEM2_FLOATS (8192 + 24576 + 2880)
#define SMEM2_BYTES (SMEM2_FLOATS * 4)

typedef unsigned long long u64;

// ---------------- device scratch ----------------
__device__ float g_pi[(size_t)MROWS * SIXH];   // PI = X @ W^T + b
__device__ float g_ht[2][NH * NB];             // h double buffer, [k][b]
__device__ u64 g_cnt_grp[NGRP];                // per-group arrival counters (monotonic)
__device__ u64 g_cnt_top;                      // top counter (+16 per step)
__device__ u64 g_bar_count;                    // one-shot init barrier

// ---------------- packed f32x2 helpers ----------------
__device__ __forceinline__ u64 pack2(float lo, float hi) {
    u64 r;
    asm("mov.b64 %0, {%1, %2};" : "=l"(r) : "f"(lo), "f"(hi));
    return r;
}
__device__ __forceinline__ void unpack2(u64 v, float& lo, float& hi) {
    asm("mov.b64 {%0, %1}, %2;" : "=f"(lo), "=f"(hi) : "l"(v));
}
__device__ __forceinline__ void fma2(u64& d, u64 a, u64 b) {
    asm("fma.rn.f32x2 %0, %1, %2, %0;" : "+l"(d) : "l"(a), "l"(b));
}

__device__ __forceinline__ float sigf(float x) {
    return 1.0f / (1.0f + __expf(-x));
}
__device__ __forceinline__ float tanh_acc(float x) {
    float e = __expf(-2.0f * fabsf(x));
    float t = (1.0f - e) / (1.0f + e);
    return x >= 0.0f ? t : -t;
}

// =====================================================================
// Phase 1: PI = X @ W^T + b (FFMA2 SGEMM) — unchanged
// =====================================================================
#define BK1 16
#define LDA1 132

__global__ void __launch_bounds__(256) gemm_pi_kernel(
    const float* __restrict__ X, const float* __restrict__ W,
    const float* __restrict__ bias)
{
    __shared__ float As[BK1 * LDA1];
    __shared__ float Bs[BK1 * LDA1];

    const int tid = threadIdx.x;
    const int tx = tid & 15, ty = tid >> 4;
    const int n0 = blockIdx.x * 128;
    const int m0 = blockIdx.y * 128;

    const float* Xp = X + (size_t)m0 * ND;
    const float* Wp = W + (size_t)n0 * ND;

    u64 accP[8][4];
#pragma unroll
    for (int i = 0; i < 8; i++)
#pragma unroll
        for (int j = 0; j < 4; j++) accP[i][j] = 0ULL;

    for (int kc = 0; kc < ND; kc += BK1) {
#pragma unroll
        for (int i = 0; i < 2; i++) {
            int idx4 = tid + 256 * i;
            int row = idx4 >> 2;
            int kq = idx4 & 3;
            float4 va = *(const float4*)(Xp + (size_t)row * ND + kc + kq * 4);
            float4 vb = *(const float4*)(Wp + (size_t)row * ND + kc + kq * 4);
            As[(kq * 4 + 0) * LDA1 + row] = va.x;
            As[(kq * 4 + 1) * LDA1 + row] = va.y;
            As[(kq * 4 + 2) * LDA1 + row] = va.z;
            As[(kq * 4 + 3) * LDA1 + row] = va.w;
            Bs[(kq * 4 + 0) * LDA1 + row] = vb.x;
            Bs[(kq * 4 + 1) * LDA1 + row] = vb.y;
            Bs[(kq * 4 + 2) * LDA1 + row] = vb.z;
            Bs[(kq * 4 + 3) * LDA1 + row] = vb.w;
        }
        __syncthreads();

#pragma unroll
        for (int k = 0; k < BK1; k++) {
            float a[8];
            *(float4*)&a[0] = *(const float4*)&As[k * LDA1 + ty * 8];
            *(float4*)&a[4] = *(const float4*)&As[k * LDA1 + ty * 8 + 4];
            ulonglong2 b01 = *(const ulonglong2*)&Bs[k * LDA1 + tx * 8];
            ulonglong2 b23 = *(const ulonglong2*)&Bs[k * LDA1 + tx * 8 + 4];
#pragma unroll
            for (int i = 0; i < 8; i++) {
                u64 ad = pack2(a[i], a[i]);
                fma2(accP[i][0], b01.x, ad);
                fma2(accP[i][1], b01.y, ad);
                fma2(accP[i][2], b23.x, ad);
                fma2(accP[i][3], b23.y, ad);
            }
        }
        __syncthreads();
    }

    float bv[8];
#pragma unroll
    for (int j = 0; j < 8; j++) bv[j] = bias[n0 + tx * 8 + j];

#pragma unroll
    for (int i = 0; i < 8; i++) {
        float c[8];
#pragma unroll
        for (int jp = 0; jp < 4; jp++)
            unpack2(accP[i][jp], c[2 * jp], c[2 * jp + 1]);
        size_t m = (size_t)m0 + ty * 8 + i;
        float* op = g_pi + m * SIXH + n0 + tx * 8;
        float4 r0 = make_float4(c[0] + bv[0], c[1] + bv[1],
                                c[2] + bv[2], c[3] + bv[3]);
        float4 r1 = make_float4(c[4] + bv[4], c[5] + bv[5],
                                c[6] + bv[6], c[7] + bv[7]);
        *(float4*)op = r0;
        *(float4*)(op + 4) = r1;
    }
}

// one-shot init barrier (monotonic, replay-safe; fence cost paid once)
__device__ __forceinline__ void init_barrier() {
    __syncthreads();
    if (threadIdx.x == 0) {
        __threadfence();
        u64 arrive = atomicAdd(&g_bar_count, 1ULL);
        u64 target = (arrive / GRID2 + 1ULL) * GRID2;
        if (arrive + 1ULL != target) {
            volatile u64* p = (volatile u64*)&g_bar_count;
            while (*p < target) { }
        }
        __threadfence();
    }
    __syncthreads();
}

// =====================================================================
// Phase 2: persistent recurrence, two-level barrier, L2-coherent h.
// =====================================================================
__global__ void __launch_bounds__(THR2, 1) lstm_rec_kernel(
    const float* __restrict__ W, const float* __restrict__ bias,
    const int* __restrict__ lengths, float* __restrict__ out)
{
    extern __shared__ float smem[];
    float* sh_h  = smem;                         // [512][16] k-major
    float* sh_wt = smem + 8192;                  // [512][48] dup-pair
    u64*   red   = (u64*)(smem + 8192 + 24576);  // [8bg][5g][4jg][9]
    __shared__ u64 s_base[2];                    // {grp_base, top_base}

    const int tid = threadIdx.x;
    const int cta = blockIdx.x;
    const int grp = cta >> 3;    // 16 groups of 8
    const int jo_base = cta * 4;

    // --- persistent duplicated W slice ---
    for (int p = tid; p < 20 * 512; p += THR2) {
        int k = p & 511, r = p >> 9;
        int g = r >> 2, jg = r & 3;
        float v = W[(size_t)(g * NH + jo_base + jg) * ND + k];
        int bi = k * 48 + jg * 12 + g * 2;
        sh_wt[bi] = v;
        sh_wt[bi + 1] = v;
    }

    // --- read counter bases BEFORE any arrivals (init barrier below) ---
    if (tid == 0) {
        u64 a, b;
        asm volatile("ld.global.cg.u64 %0, [%1];" : "=l"(a)
                     : "l"(&g_cnt_grp[grp]) : "memory");
        asm volatile("ld.global.cg.u64 %0, [%1];" : "=l"(b)
                     : "l"(&g_cnt_top) : "memory");
        s_base[0] = a;
        s_base[1] = b;
    }

    // --- combine-thread persistent state ---
    int b_c = 0, jo_c = 0, len_c = 0;
    float bias5[5] = {0, 0, 0, 0, 0};
    float c_reg = 0.0f;
    const float* pi_row = g_pi;
    if (tid < 64) {
        b_c = tid >> 2;
        jo_c = jo_base + (tid & 3);
#pragma unroll
        for (int g = 0; g < 5; g++) bias5[g] = bias[g * NH + jo_c];
        len_c = lengths[b_c];
        pi_row = g_pi + (size_t)b_c * NT * SIXH + jo_c;
    }

    // --- publish h_0 = zeros; init barrier makes it visible everywhere ---
    if (tid < 64) g_ht[0][cta * 64 + tid] = 0.0f;
    init_barrier();

    const u64 grp_base = s_base[0];
    const u64 top_base = s_base[1];

    // prefetch PI(t=0)
    float pi5[5] = {0, 0, 0, 0, 0}, pi6 = 0.0f;
    if (tid < 64) {
#pragma unroll
        for (int g = 0; g < 5; g++) pi5[g] = pi_row[g * NH];
        pi6 = pi_row[5 * NH];
    }

    const int warp = tid >> 5, lane = tid & 31;
    const int bg = lane & 7;
    const int jg = lane >> 3;
    const u64*   hp0 = (const u64*)sh_h + (size_t)warp * 64 * 8 + bg;
    const float* wp0 = sh_wt + (size_t)warp * 64 * 48 + jg * 12;

    for (int t = 0; t < NT; t++) {
        const float* hbuf = g_ht[t & 1];
        float* hnext = g_ht[(t & 1) ^ 1];

        // --- stage this warp's own 64-row h slab (L2-direct, warp-local) ---
        {
            const float4* src = (const float4*)(hbuf + warp * 1024);
            float4* dst = (float4*)(sh_h + warp * 1024);
#pragma unroll
            for (int i = 0; i < 8; i++)
                dst[i * 32 + lane] = __ldcg(src + i * 32 + lane);
        }
        __syncwarp();

        // --- K-split packed GEMM: {b0,b1} x 5 gates per lane, 64 k ---
        u64 acc0 = 0, acc1 = 0, acc2 = 0, acc3 = 0, acc4 = 0;
        {
            const u64* hp = hp0;
            const float* wp = wp0;
#pragma unroll 8
            for (int kk = 0; kk < 64; kk++) {
                u64 hd = *hp;                                  // {h_b0, h_b1}
                ulonglong2 w01 = *(const ulonglong2*)wp;       // {w0,w0},{w1,w1}
                ulonglong2 w23 = *(const ulonglong2*)(wp + 4); // {w2,w2},{w3,w3}
                u64 w44 = *(const u64*)(wp + 8);               // {w4,w4}
                fma2(acc0, hd, w01.x);
                fma2(acc1, hd, w01.y);
                fma2(acc2, hd, w23.x);
                fma2(acc3, hd, w23.y);
                fma2(acc4, hd, w44);
                hp += 8;
                wp += 48;
            }
        }

        // write pair partials: red[((bg*5+g)*4+jg)*9 + warp]
        {
            int rb = (bg * 5) * 4 + jg;
            red[(rb + 0) * 9 + warp] = acc0;
            red[(rb + 4) * 9 + warp] = acc1;
            red[(rb + 8) * 9 + warp] = acc2;
            red[(rb + 12) * 9 + warp] = acc3;
            red[(rb + 16) * 9 + warp] = acc4;
        }
        __syncthreads();

        // --- reduce across 8 warps + gate math + publish (tid<64) ---
        if (tid < 64) {
            const float* redf = (const float*)red;
            int bgc = b_c >> 1, e = b_c & 1, q = tid & 3;
            float gv[5];
#pragma unroll
            for (int g = 0; g < 5; g++) {
                const float* rp = redf + (((bgc * 5 + g) * 4 + q) * 9) * 2 + e;
                float s = ((rp[0] + rp[2]) + (rp[4] + rp[6])) +
                          ((rp[8] + rp[10]) + (rp[12] + rp[14]));
                gv[g] = s + bias5[g] + pi5[g];
            }
            float ig = sigf(gv[0]);
            float fg = sigf(gv[1]);
            float mi = tanh_acc(gv[2]);
            float og = sigf(gv[3]);
            float hwg = sigf(gv[4]);
            float mem = fmaf(ig, mi, fg * c_reg);
            float o_ = og * tanh_acc(mem);
            o_ = fmaf(hwg, o_ - pi6, pi6);
            if (t >= len_c) { o_ = 0.0f; mem = 0.0f; }
            c_reg = mem;

            hnext[jo_c * 16 + b_c] = o_;   // transposed h slice first
            out[((size_t)b_c * NT + t) * NH + jo_c] = o_;
        }

        // --- arrive (two-level): group acq_rel add, completer bumps top ---
        if (tid == 0) {
            u64 old;
            asm volatile("atom.acq_rel.gpu.global.add.u64 %0, [%1], 1;"
                         : "=l"(old) : "l"(&g_cnt_grp[grp]) : "memory");
            if (old + 1ULL == grp_base + (u64)GRPSZ * (u64)(t + 1)) {
                asm volatile("red.release.gpu.global.add.u64 [%0], 1;"
                             :: "l"(&g_cnt_top) : "memory");
            }
        }

        // prefetch PI(t+1): flies while thread0 spins
        if (tid < 64 && t + 1 < NT) {
            const float* pr = pi_row + (size_t)(t + 1) * SIXH;
#pragma unroll
            for (int g = 0; g < 5; g++) pi5[g] = pr[g * NH];
            pi6 = pr[5 * NH];
        }

        // --- spin on top counter (acquire: publishes all CTAs' h stores) ---
        if (tid == 0) {
            u64 tgt = top_base + (u64)NGRP * (u64)(t + 1);
            u64 v;
            do {
                asm volatile("ld.global.acquire.gpu.u64 %0, [%1];"
                             : "=l"(v) : "l"(&g_cnt_top) : "memory");
            } while (v < tgt);
        }
        __syncthreads();
    }
}

// =====================================================================
// launch
// =====================================================================
extern "C" void kernel_launch(void* const* d_in, const int* in_sizes, int n_in,
                              void* d_out, int out_size) {
    const float* x = (const float*)d_in[0];
    const int* lengths = (const int*)d_in[1];
    const float* W = (const float*)d_in[2];
    const float* bias = (const float*)d_in[3];
    float* out = (float*)d_out;

    static bool attr_done = false;
    if (!attr_done) {
        cudaFuncSetAttribute(lstm_rec_kernel,
                             cudaFuncAttributeMaxDynamicSharedMemorySize,
                             SMEM2_BYTES);
        attr_done = true;
    }

    dim3 g1(SIXH / 128, MROWS / 128);  // (24, 256)
    gemm_pi_kernel<<<g1, 256>>>(x, W, bias);
    lstm_rec_kernel<<<GRID2, THR2, SMEM2_BYTES>>>(W, bias, lengths, out);
}

// round 9
// speedup vs baseline: 2.8161x; 1.1953x over previous
#include <cuda_runtime.h>
#include <math.h>

#define NB 16
#define NT 2048
#define ND 512
#define NH 512
#define SIXH 3072
#define MROWS (NB * NT)   // 32768

#define NREC 128          // recurrence CTAs
#define NGEMM 128         // gemm worker CTAs
#define NBLK (NREC + NGEMM)
#define THR2 256

#define NSLAB 16
#define TILES_TOTAL 6144      // 16 b x 16 tau x 24 n
#define TILES_PER_SLAB 384    // 16 b x 24 n

// recurrence smem: sh_h 512*16 | sh_wt 512*32 | red 320*9 floats
#define SMEM2_FLOATS (8192 + 16384 + 2880)
#define SMEM2_BYTES (SMEM2_FLOATS * 4)

typedef unsigned long long u64;

// ---------------- device scratch ----------------
__device__ float g_pi[(size_t)MROWS * SIXH];   // PI = X @ W^T + b
__device__ float g_ht[2][NH * NB];             // h double buffer, [k][b]
__device__ u64 g_bar_count;                    // per-step barrier (128 rec CTAs)
__device__ u64 g_init_cnt;                     // init barrier (256 CTAs)
__device__ u64 g_slab_cnt[NSLAB];              // monotonic slab-complete counters

// ---------------- packed f32x2 helpers ----------------
__device__ __forceinline__ u64 pack2(float lo, float hi) {
    u64 r;
    asm("mov.b64 %0, {%1, %2};" : "=l"(r) : "f"(lo), "f"(hi));
    return r;
}
__device__ __forceinline__ void unpack2(u64 v, float& lo, float& hi) {
    asm("mov.b64 {%0, %1}, %2;" : "=f"(lo), "=f"(hi) : "l"(v));
}
__device__ __forceinline__ void fma2(u64& d, u64 a, u64 b) {
    asm("fma.rn.f32x2 %0, %1, %2, %0;" : "+l"(d) : "l"(a), "l"(b));
}

__device__ __forceinline__ float sigf(float x) {
    return 1.0f / (1.0f + __expf(-x));
}
__device__ __forceinline__ float tanh_acc(float x) {
    float e = __expf(-2.0f * fabsf(x));
    float t = (1.0f - e) / (1.0f + e);
    return x >= 0.0f ? t : -t;
}

// init barrier across ALL 256 CTAs (monotonic, replay-safe)
__device__ __forceinline__ void init_barrier_all() {
    __syncthreads();
    if (threadIdx.x == 0) {
        __threadfence();
        u64 arrive = atomicAdd(&g_init_cnt, 1ULL);
        u64 target = (arrive / NBLK + 1ULL) * NBLK;
        if (arrive + 1ULL != target) {
            volatile u64* p = (volatile u64*)&g_init_cnt;
            while (*p < target) { }
        }
        __threadfence();
    }
    __syncthreads();
}

// per-step barrier across the 128 recurrence CTAs (R3 verbatim)
__device__ __forceinline__ void grid_barrier() {
    __syncthreads();
    if (threadIdx.x == 0) {
        __threadfence();
        u64 arrive = atomicAdd(&g_bar_count, 1ULL);
        u64 target = (arrive / NREC + 1ULL) * NREC;
        if (arrive + 1ULL != target) {
            volatile u64* p = (volatile u64*)&g_bar_count;
            while (*p < target) { }
        }
        __threadfence();
    }
    __syncthreads();
}

#define BK1 16
#define LDA1 132

// =====================================================================
// Fused kernel: blocks 0-127 = recurrence (R3 core), blocks 128-255 =
// gemm workers producing g_pi slab-by-slab (tau-ascending) with
// monotonic completion counters.
// =====================================================================
__global__ void __launch_bounds__(THR2, 2) fused_lstm_kernel(
    const float* __restrict__ X, const float* __restrict__ W,
    const float* __restrict__ bias, const int* __restrict__ lengths,
    float* __restrict__ out)
{
    extern __shared__ float smem[];
    const int tid = threadIdx.x;
    const int cta = blockIdx.x;

    if (cta >= NREC) {
        // ================== GEMM worker ==================
        float* As = smem;
        float* Bs = smem + BK1 * LDA1;
        const int w = cta - NREC;
        const int tx = tid & 15, ty = tid >> 4;

        // wait until all recurrence CTAs have read slab-counter bases
        init_barrier_all();

        for (int it = w; it < TILES_TOTAL; it += NGEMM) {
            const int tau = it / TILES_PER_SLAB;
            const int r = it % TILES_PER_SLAB;
            const int b = r / 24;
            const int n = r % 24;
            const int n0 = n * 128;
            const size_t m0 = (size_t)b * NT + (size_t)tau * 128;

            const float* Xp = X + m0 * ND;
            const float* Wp = W + (size_t)n0 * ND;

            u64 accP[8][4];
#pragma unroll
            for (int i = 0; i < 8; i++)
#pragma unroll
                for (int j = 0; j < 4; j++) accP[i][j] = 0ULL;

            for (int kc = 0; kc < ND; kc += BK1) {
#pragma unroll
                for (int i = 0; i < 2; i++) {
                    int idx4 = tid + 256 * i;
                    int row = idx4 >> 2;
                    int kq = idx4 & 3;
                    float4 va = *(const float4*)(Xp + (size_t)row * ND + kc + kq * 4);
                    float4 vb = *(const float4*)(Wp + (size_t)row * ND + kc + kq * 4);
                    As[(kq * 4 + 0) * LDA1 + row] = va.x;
                    As[(kq * 4 + 1) * LDA1 + row] = va.y;
                    As[(kq * 4 + 2) * LDA1 + row] = va.z;
                    As[(kq * 4 + 3) * LDA1 + row] = va.w;
                    Bs[(kq * 4 + 0) * LDA1 + row] = vb.x;
                    Bs[(kq * 4 + 1) * LDA1 + row] = vb.y;
                    Bs[(kq * 4 + 2) * LDA1 + row] = vb.z;
                    Bs[(kq * 4 + 3) * LDA1 + row] = vb.w;
                }
                __syncthreads();
#pragma unroll
                for (int k = 0; k < BK1; k++) {
                    float a[8];
                    *(float4*)&a[0] = *(const float4*)&As[k * LDA1 + ty * 8];
                    *(float4*)&a[4] = *(const float4*)&As[k * LDA1 + ty * 8 + 4];
                    ulonglong2 b01 = *(const ulonglong2*)&Bs[k * LDA1 + tx * 8];
                    ulonglong2 b23 = *(const ulonglong2*)&Bs[k * LDA1 + tx * 8 + 4];
#pragma unroll
                    for (int i = 0; i < 8; i++) {
                        u64 ad = pack2(a[i], a[i]);
                        fma2(accP[i][0], b01.x, ad);
                        fma2(accP[i][1], b01.y, ad);
                        fma2(accP[i][2], b23.x, ad);
                        fma2(accP[i][3], b23.y, ad);
                    }
                }
                __syncthreads();
            }

            float bv[8];
#pragma unroll
            for (int j = 0; j < 8; j++) bv[j] = bias[n0 + tx * 8 + j];
#pragma unroll
            for (int i = 0; i < 8; i++) {
                float c[8];
#pragma unroll
                for (int jp = 0; jp < 4; jp++)
                    unpack2(accP[i][jp], c[2 * jp], c[2 * jp + 1]);
                size_t m = m0 + ty * 8 + i;
                float* op = g_pi + m * SIXH + n0 + tx * 8;
                float4 r0 = make_float4(c[0] + bv[0], c[1] + bv[1],
                                        c[2] + bv[2], c[3] + bv[3]);
                float4 r1 = make_float4(c[4] + bv[4], c[5] + bv[5],
                                        c[6] + bv[6], c[7] + bv[7]);
                *(float4*)op = r0;
                *(float4*)(op + 4) = r1;
            }

            // publish: every thread drains its own stores, then one release-add
            __threadfence();
            __syncthreads();
            if (tid == 0) {
                asm volatile("red.release.gpu.global.add.u64 [%0], 1;"
                             :: "l"(&g_slab_cnt[tau]) : "memory");
            }
        }
        return;
    }

    // ============ recurrence CTA (R3 core + slab gating) ============
    float* sh_h  = smem;                   // [512][16]  k-major
    float* sh_wt = smem + 8192;            // [512][32]  (jg*8+u padded)
    float* red   = smem + 8192 + 16384;    // [320][9] floats (R3 layout)
    __shared__ u64 s_slab[NSLAB];

    const int jo_base = cta * 4;

    // persistent W slice: sh_wt[k*32 + jg*8 + u] = W[u*NH+jo_base+jg][k]
    for (int p = tid; p < 20 * 512; p += THR2) {
        int k = p & 511;
        int r = p >> 9;
        int u = r >> 2;
        int jg = r & 3;
        sh_wt[k * 32 + jg * 8 + u] =
            W[(size_t)(u * NH + jo_base + jg) * ND + k];
    }

    // read slab-counter bases BEFORE any gemm worker increments
    if (tid < NSLAB) {
        u64 v;
        asm volatile("ld.global.cg.u64 %0, [%1];" : "=l"(v)
                     : "l"(&g_slab_cnt[tid]) : "memory");
        s_slab[tid] = v;
    }

    // combine-thread persistent state
    int b_c = 0, jo_c = 0, len_c = 0;
    float bias5[5] = {0, 0, 0, 0, 0};
    float c_reg = 0.0f;
    if (tid < 64) {
        b_c = tid >> 2;
        jo_c = jo_base + (tid & 3);
#pragma unroll
        for (int g = 0; g < 5; g++) bias5[g] = bias[g * NH + jo_c];
        len_c = lengths[b_c];
    }

    // publish h_0 = zeros; init barrier releases gemm workers too
    if (tid < 64) g_ht[0][cta * 64 + tid] = 0.0f;
    init_barrier_all();

    const int warp = tid >> 5, lane = tid & 31;
    const int bg = lane & 7;   // batch pair {2bg, 2bg+1}
    const int jg = lane >> 3;  // channel offset within CTA
    const u64*   hp0 = (const u64*)sh_h + (size_t)warp * 64 * 8 + bg;
    const float* wp0 = sh_wt + (size_t)warp * 64 * 32 + jg * 8;

    for (int t = 0; t < NT; t++) {
        // slab gate: before consuming PI of a new 128-step slab
        if ((t & 127) == 0) {
            if (tid == 0) {
                int tau = t >> 7;
                u64 tgt = s_slab[tau] + (u64)TILES_PER_SLAB;
                u64 v;
                do {
                    asm volatile("ld.global.acquire.gpu.u64 %0, [%1];"
                                 : "=l"(v) : "l"(&g_slab_cnt[tau]) : "memory");
                } while (v < tgt);
            }
            __syncthreads();
        }

        const float* hbuf = g_ht[t & 1];
        float* hnext = g_ht[(t & 1) ^ 1];

        // prefetch PI(t) early (latency hides behind staging + gemm)
        float pi5[5] = {0, 0, 0, 0, 0}, pi6 = 0.0f;
        if (tid < 64) {
            const float* pr = g_pi + ((size_t)b_c * NT + t) * SIXH + jo_c;
#pragma unroll
            for (int g = 0; g < 5; g++) pi5[g] = pr[g * NH];
            pi6 = pr[5 * NH];
        }

        // stage h (already transposed [k][b]) -> straight coalesced copy
#pragma unroll
        for (int i = 0; i < 8; i++) {
            int off = tid * 4 + i * 1024;
            *(float4*)&sh_h[off] = *(const float4*)&hbuf[off];
        }
        __syncthreads();

        // K-split packed-FFMA2 partial GEMM: 2b x 5gate per lane, 64 k
        u64 a01_b0 = 0, a23_b0 = 0, a01_b1 = 0, a23_b1 = 0, a4 = 0;
        {
            const u64* hp = hp0;
            const float* wp = wp0;
#pragma unroll 8
            for (int kk = 0; kk < 64; kk++) {
                u64 hd = *hp;                                // {h_b0, h_b1}
                ulonglong2 wv = *(const ulonglong2*)wp;      // {w0,w1},{w2,w3}
                float w4 = wp[4];
                float h0, h1;
                unpack2(hd, h0, h1);
                u64 h00 = pack2(h0, h0);
                u64 h11 = pack2(h1, h1);
                u64 w44 = pack2(w4, w4);
                fma2(a01_b0, wv.x, h00);
                fma2(a23_b0, wv.y, h00);
                fma2(a01_b1, wv.x, h11);
                fma2(a23_b1, wv.y, h11);
                fma2(a4, hd, w44);                           // {b0,b1} x w4
                hp += 8;
                wp += 32;
            }
        }

        // unpack and write partials (exact R3 layout: red[row*9+warp])
        {
            float v0, v1, v2, v3, v4b0, v4b1, u0, u1, u2, u3;
            unpack2(a01_b0, v0, v1);
            unpack2(a23_b0, v2, v3);
            unpack2(a01_b1, u0, u1);
            unpack2(a23_b1, u2, u3);
            unpack2(a4, v4b0, v4b1);
            int rb0 = (2 * bg) * 20 + jg;
            int rb1 = (2 * bg + 1) * 20 + jg;
            red[(rb0 + 0) * 9 + warp] = v0;
            red[(rb0 + 4) * 9 + warp] = v1;
            red[(rb0 + 8) * 9 + warp] = v2;
            red[(rb0 + 12) * 9 + warp] = v3;
            red[(rb0 + 16) * 9 + warp] = v4b0;
            red[(rb1 + 0) * 9 + warp] = u0;
            red[(rb1 + 4) * 9 + warp] = u1;
            red[(rb1 + 8) * 9 + warp] = u2;
            red[(rb1 + 12) * 9 + warp] = u3;
            red[(rb1 + 16) * 9 + warp] = v4b1;
        }
        __syncthreads();

        // reduce across 8 warps + gate math (64 threads)
        if (tid < 64) {
            float gv[5];
#pragma unroll
            for (int g = 0; g < 5; g++) {
                int o = b_c * 20 + g * 4 + (tid & 3);
                const float* rp = red + o * 9;
                float s = ((rp[0] + rp[1]) + (rp[2] + rp[3])) +
                          ((rp[4] + rp[5]) + (rp[6] + rp[7]));
                gv[g] = s + bias5[g] + pi5[g];
            }
            float ig = sigf(gv[0]);
            float fg = sigf(gv[1]);
            float mi = tanh_acc(gv[2]);
            float og = sigf(gv[3]);
            float hwg = sigf(gv[4]);
            float mem = fmaf(ig, mi, fg * c_reg);
            float o_ = og * tanh_acc(mem);
            o_ = fmaf(hwg, o_ - pi6, pi6);
            if (t >= len_c) { o_ = 0.0f; mem = 0.0f; }
            c_reg = mem;

            hnext[jo_c * 16 + b_c] = o_;   // transposed for next step
            out[((size_t)b_c * NT + t) * NH + jo_c] = o_;
        }
        grid_barrier();
    }
}

// =====================================================================
// launch
// =====================================================================
extern "C" void kernel_launch(void* const* d_in, const int* in_sizes, int n_in,
                              void* d_out, int out_size) {
    const float* x = (const float*)d_in[0];
    const int* lengths = (const int*)d_in[1];
    const float* W = (const float*)d_in[2];
    const float* bias = (const float*)d_in[3];
    float* out = (float*)d_out;

    static bool attr_done = false;
    if (!attr_done) {
        cudaFuncSetAttribute(fused_lstm_kernel,
                             cudaFuncAttributeMaxDynamicSharedMemorySize,
                             SMEM2_BYTES);
        attr_done = true;
    }

    fused_lstm_kernel<<<NBLK, THR2, SMEM2_BYTES>>>(x, W, bias, lengths, out);
}

// round 11
// speedup vs baseline: 2.9423x; 1.0448x over previous
#include <cuda_runtime.h>
#include <math.h>

#define NB 16
#define NT 2048
#define ND 512
#define NH 512
#define SIXH 3072
#define MROWS (NB * NT)   // 32768

#define NREC 64           // recurrence CTAs (8 channels each)
#define NGEMM 84          // gemm worker CTAs
#define NBLK (NREC + NGEMM)   // 148 == SM count -> all co-resident @ 1 CTA/SM
#define THR2 256

#define NSLAB 16
#define TILES_TOTAL 6144      // 16 b x 16 tau x 24 n
#define TILES_PER_SLAB 384    // 16 b x 24 n

// recurrence smem: sh_h 512*16 | sh_wt 512*48 | red 320*9 u64 (pairs)
// NOTE: dynamic smem is launch-wide; at 150.5KB/block occupancy is 1 CTA/SM,
// hence grid must be <= 148 for the persistent barriers to be deadlock-free.
#define SMEM2_FLOATS (8192 + 24576 + 5760)
#define SMEM2_BYTES (SMEM2_FLOATS * 4)

typedef unsigned long long u64;

// ---------------- device scratch ----------------
__device__ float g_pi[(size_t)MROWS * SIXH];   // PI = X @ W^T + b
__device__ float g_ht[2][NH * NB];             // h double buffer, [k][b]
__device__ u64 g_bar_count;                    // per-step barrier (64 rec CTAs)
__device__ u64 g_init_cnt;                     // init barrier (148 CTAs)
__device__ u64 g_slab_cnt[NSLAB];              // monotonic slab-complete counters

// ---------------- packed f32x2 helpers ----------------
__device__ __forceinline__ u64 pack2(float lo, float hi) {
    u64 r;
    asm("mov.b64 %0, {%1, %2};" : "=l"(r) : "f"(lo), "f"(hi));
    return r;
}
__device__ __forceinline__ void unpack2(u64 v, float& lo, float& hi) {
    asm("mov.b64 {%0, %1}, %2;" : "=f"(lo), "=f"(hi) : "l"(v));
}
__device__ __forceinline__ void fma2(u64& d, u64 a, u64 b) {
    asm("fma.rn.f32x2 %0, %1, %2, %0;" : "+l"(d) : "l"(a), "l"(b));
}

__device__ __forceinline__ float sigf(float x) {
    return 1.0f / (1.0f + __expf(-x));
}
__device__ __forceinline__ float tanh_acc(float x) {
    float e = __expf(-2.0f * fabsf(x));
    float t = (1.0f - e) / (1.0f + e);
    return x >= 0.0f ? t : -t;
}

// init barrier across ALL 148 CTAs (monotonic, replay-safe)
__device__ __forceinline__ void init_barrier_all() {
    __syncthreads();
    if (threadIdx.x == 0) {
        __threadfence();
        u64 arrive = atomicAdd(&g_init_cnt, 1ULL);
        u64 target = (arrive / NBLK + 1ULL) * NBLK;
        if (arrive + 1ULL != target) {
            volatile u64* p = (volatile u64*)&g_init_cnt;
            while (*p < target) { }
        }
        __threadfence();
    }
    __syncthreads();
}

// per-step barrier across the 64 recurrence CTAs
__device__ __forceinline__ void grid_barrier() {
    __syncthreads();
    if (threadIdx.x == 0) {
        __threadfence();
        u64 arrive = atomicAdd(&g_bar_count, 1ULL);
        u64 target = (arrive / NREC + 1ULL) * NREC;
        if (arrive + 1ULL != target) {
            volatile u64* p = (volatile u64*)&g_bar_count;
            while (*p < target) { }
        }
        __threadfence();
    }
    __syncthreads();
}

#define BK1 16
#define LDA1 132

// =====================================================================
// Fused kernel: blocks 0-63 = recurrence (8 channels/CTA), blocks
// 64-147 = gemm workers filling g_pi slab-by-slab (tau-ascending).
// =====================================================================
__global__ void __launch_bounds__(THR2, 1) fused_lstm_kernel(
    const float* __restrict__ X, const float* __restrict__ W,
    const float* __restrict__ bias, const int* __restrict__ lengths,
    float* __restrict__ out)
{
    extern __shared__ float smem[];
    const int tid = threadIdx.x;
    const int cta = blockIdx.x;

    if (cta >= NREC) {
        // ================== GEMM worker ==================
        float* As = smem;
        float* Bs = smem + BK1 * LDA1;
        const int w = cta - NREC;
        const int tx = tid & 15, ty = tid >> 4;

        init_barrier_all();

        for (int it = w; it < TILES_TOTAL; it += NGEMM) {
            const int tau = it / TILES_PER_SLAB;
            const int r = it % TILES_PER_SLAB;
            const int b = r / 24;
            const int n = r % 24;
            const int n0 = n * 128;
            const size_t m0 = (size_t)b * NT + (size_t)tau * 128;

            const float* Xp = X + m0 * ND;
            const float* Wp = W + (size_t)n0 * ND;

            u64 accP[8][4];
#pragma unroll
            for (int i = 0; i < 8; i++)
#pragma unroll
                for (int j = 0; j < 4; j++) accP[i][j] = 0ULL;

            for (int kc = 0; kc < ND; kc += BK1) {
#pragma unroll
                for (int i = 0; i < 2; i++) {
                    int idx4 = tid + 256 * i;
                    int row = idx4 >> 2;
                    int kq = idx4 & 3;
                    float4 va = *(const float4*)(Xp + (size_t)row * ND + kc + kq * 4);
                    float4 vb = *(const float4*)(Wp + (size_t)row * ND + kc + kq * 4);
                    As[(kq * 4 + 0) * LDA1 + row] = va.x;
                    As[(kq * 4 + 1) * LDA1 + row] = va.y;
                    As[(kq * 4 + 2) * LDA1 + row] = va.z;
                    As[(kq * 4 + 3) * LDA1 + row] = va.w;
                    Bs[(kq * 4 + 0) * LDA1 + row] = vb.x;
                    Bs[(kq * 4 + 1) * LDA1 + row] = vb.y;
                    Bs[(kq * 4 + 2) * LDA1 + row] = vb.z;
                    Bs[(kq * 4 + 3) * LDA1 + row] = vb.w;
                }
                __syncthreads();
#pragma unroll
                for (int k = 0; k < BK1; k++) {
                    float a[8];
                    *(float4*)&a[0] = *(const float4*)&As[k * LDA1 + ty * 8];
                    *(float4*)&a[4] = *(const float4*)&As[k * LDA1 + ty * 8 + 4];
                    ulonglong2 b01 = *(const ulonglong2*)&Bs[k * LDA1 + tx * 8];
                    ulonglong2 b23 = *(const ulonglong2*)&Bs[k * LDA1 + tx * 8 + 4];
#pragma unroll
                    for (int i = 0; i < 8; i++) {
                        u64 ad = pack2(a[i], a[i]);
                        fma2(accP[i][0], b01.x, ad);
                        fma2(accP[i][1], b01.y, ad);
                        fma2(accP[i][2], b23.x, ad);
                        fma2(accP[i][3], b23.y, ad);
                    }
                }
                __syncthreads();
            }

            float bv[8];
#pragma unroll
            for (int j = 0; j < 8; j++) bv[j] = bias[n0 + tx * 8 + j];
#pragma unroll
            for (int i = 0; i < 8; i++) {
                float c[8];
#pragma unroll
                for (int jp = 0; jp < 4; jp++)
                    unpack2(accP[i][jp], c[2 * jp], c[2 * jp + 1]);
                size_t m = m0 + ty * 8 + i;
                float* op = g_pi + m * SIXH + n0 + tx * 8;
                float4 r0 = make_float4(c[0] + bv[0], c[1] + bv[1],
                                        c[2] + bv[2], c[3] + bv[3]);
                float4 r1 = make_float4(c[4] + bv[4], c[5] + bv[5],
                                        c[6] + bv[6], c[7] + bv[7]);
                *(float4*)op = r0;
                *(float4*)(op + 4) = r1;
            }

            __threadfence();
            __syncthreads();
            if (tid == 0) {
                asm volatile("red.release.gpu.global.add.u64 [%0], 1;"
                             :: "l"(&g_slab_cnt[tau]) : "memory");
            }
        }
        return;
    }

    // ============ recurrence CTA: 8 channels, channel-pair packing ============
    float* sh_h  = smem;                   // [512][16]  k-major
    float* sh_wt = smem + 8192;            // [512][48]: [k][jp*12 + g*2 + c]
    u64*   red   = (u64*)(smem + 8192 + 24576);  // [16b*5g*4jp][9] pairs {c0,c1}
    __shared__ u64 s_slab[NSLAB];

    const int jo_base = cta * 8;

    // persistent W slice: sh_wt[k*48 + jp*12 + g*2 + c] = W[g*NH+jo_base+2jp+c][k]
    for (int p = tid; p < 40 * 512; p += THR2) {
        int k = p & 511;
        int r = p >> 9;          // 0..39
        int g = r / 8;
        int rc = r & 7;
        int jp = rc >> 1, c = rc & 1;
        sh_wt[k * 48 + jp * 12 + g * 2 + c] =
            W[(size_t)(g * NH + jo_base + 2 * jp + c) * ND + k];
    }

    if (tid < NSLAB) {
        u64 v;
        asm volatile("ld.global.cg.u64 %0, [%1];" : "=l"(v)
                     : "l"(&g_slab_cnt[tid]) : "memory");
        s_slab[tid] = v;
    }

    // combine-thread persistent state (128 threads: b_c = tid>>3, ch = tid&7)
    int b_c = 0, jo_c = 0, len_c = 0;
    float bias5[5] = {0, 0, 0, 0, 0};
    float c_reg = 0.0f;
    if (tid < 128) {
        b_c = tid >> 3;
        jo_c = jo_base + (tid & 7);
#pragma unroll
        for (int g = 0; g < 5; g++) bias5[g] = bias[g * NH + jo_c];
        len_c = lengths[b_c];
    }

    // publish h_0 = zeros (128 values per CTA); init barrier releases workers
    if (tid < 128) g_ht[0][cta * 128 + tid] = 0.0f;
    init_barrier_all();

    const int warp = tid >> 5, lane = tid & 31;
    const int bg = lane & 7;   // batch pair {2bg, 2bg+1}
    const int jp = lane >> 3;  // channel pair {2jp, 2jp+1}
    const u64*   hp0 = (const u64*)sh_h + (size_t)warp * 64 * 8 + bg;
    const float* wp0 = sh_wt + (size_t)warp * 64 * 48 + jp * 12;

    for (int t = 0; t < NT; t++) {
        // slab gate before each 128-step PI slab
        if ((t & 127) == 0) {
            if (tid == 0) {
                int tau = t >> 7;
                u64 tgt = s_slab[tau] + (u64)TILES_PER_SLAB;
                u64 v;
                do {
                    asm volatile("ld.global.acquire.gpu.u64 %0, [%1];"
                                 : "=l"(v) : "l"(&g_slab_cnt[tau]) : "memory");
                } while (v < tgt);
            }
            __syncthreads();
        }

        const float* hbuf = g_ht[t & 1];
        float* hnext = g_ht[(t & 1) ^ 1];

        // prefetch PI(t)
        float pi5[5] = {0, 0, 0, 0, 0}, pi6 = 0.0f;
        if (tid < 128) {
            const float* pr = g_pi + ((size_t)b_c * NT + t) * SIXH + jo_c;
#pragma unroll
            for (int g = 0; g < 5; g++) pi5[g] = pr[g * NH];
            pi6 = pr[5 * NH];
        }

        // stage full h [k][b] -> coalesced copy (32KB)
#pragma unroll
        for (int i = 0; i < 8; i++) {
            int off = tid * 4 + i * 1024;
            *(float4*)&sh_h[off] = *(const float4*)&hbuf[off];
        }
        __syncthreads();

        // K-split packed GEMM: 2 batches x 5 gates x {2 channels}, 64 k
        u64 acc[10];
#pragma unroll
        for (int i = 0; i < 10; i++) acc[i] = 0ULL;
        {
            const u64* hp = hp0;
            const float* wp = wp0;
#pragma unroll 8
            for (int kk = 0; kk < 64; kk++) {
                u64 hd = *hp;                                  // {h_b0, h_b1}
                float h0, h1;
                unpack2(hd, h0, h1);
                u64 h00 = pack2(h0, h0);
                u64 h11 = pack2(h1, h1);
                ulonglong2 wA = *(const ulonglong2*)wp;        // g0,g1: {c0,c1}
                ulonglong2 wB = *(const ulonglong2*)(wp + 4);  // g2,g3
                u64 wC = *(const u64*)(wp + 8);                // g4
                fma2(acc[0], wA.x, h00);
                fma2(acc[1], wA.y, h00);
                fma2(acc[2], wB.x, h00);
                fma2(acc[3], wB.y, h00);
                fma2(acc[4], wC, h00);
                fma2(acc[5], wA.x, h11);
                fma2(acc[6], wA.y, h11);
                fma2(acc[7], wB.x, h11);
                fma2(acc[8], wB.y, h11);
                fma2(acc[9], wC, h11);
                hp += 8;
                wp += 48;
            }
        }

        // write pair partials: red[((b*5+g)*4+jp)*9 + warp] = {c0,c1}
        {
            int rb0 = ((2 * bg) * 5) * 4 + jp;
            int rb1 = ((2 * bg + 1) * 5) * 4 + jp;
#pragma unroll
            for (int g = 0; g < 5; g++) {
                red[(rb0 + g * 4) * 9 + warp] = acc[g];
                red[(rb1 + g * 4) * 9 + warp] = acc[5 + g];
            }
        }
        __syncthreads();

        // reduce across 8 warps + gate math (128 threads)
        if (tid < 128) {
            const float* redf = (const float*)red;
            int jpc = (tid & 7) >> 1, e = tid & 1;
            float gv[5];
#pragma unroll
            for (int g = 0; g < 5; g++) {
                const float* rp = redf + (((b_c * 5 + g) * 4 + jpc) * 9) * 2 + e;
                float s = ((rp[0] + rp[2]) + (rp[4] + rp[6])) +
                          ((rp[8] + rp[10]) + (rp[12] + rp[14]));
                gv[g] = s + bias5[g] + pi5[g];
            }
            float ig = sigf(gv[0]);
            float fg = sigf(gv[1]);
            float mi = tanh_acc(gv[2]);
            float og = sigf(gv[3]);
            float hwg = sigf(gv[4]);
            float mem = fmaf(ig, mi, fg * c_reg);
            float o_ = og * tanh_acc(mem);
            o_ = fmaf(hwg, o_ - pi6, pi6);
            if (t >= len_c) { o_ = 0.0f; mem = 0.0f; }
            c_reg = mem;

            hnext[jo_c * 16 + b_c] = o_;   // transposed for next step
            out[((size_t)b_c * NT + t) * NH + jo_c] = o_;
        }
        grid_barrier();
    }
}

// =====================================================================
// launch
// =====================================================================
extern "C" void kernel_launch(void* const* d_in, const int* in_sizes, int n_in,
                              void* d_out, int out_size) {
    const float* x = (const float*)d_in[0];
    const int* lengths = (const int*)d_in[1];
    const float* W = (const float*)d_in[2];
    const float* bias = (const float*)d_in[3];
    float* out = (float*)d_out;

    static bool attr_done = false;
    if (!attr_done) {
        cudaFuncSetAttribute(fused_lstm_kernel,
                             cudaFuncAttributeMaxDynamicSharedMemorySize,
                             SMEM2_BYTES);
        attr_done = true;
    }

    fused_lstm_kernel<<<NBLK, THR2, SMEM2_BYTES>>>(x, W, bias, lengths, out);
}